// round 17
// baseline (speedup 1.0000x reference)
#include <cuda_runtime.h>
#include <cstdint>

// CRF loss via bidirectional scaled forward algorithm, f32x2-packed inner loop.
// One 128-thread CTA per batch row: warps 0-1 alpha forward (t=0..m), warps
// 2-3 beta backward (t=len-1..m); Z = sum_i alpha_m[i]*beta_m[i]. Each group
// has its own named barrier and tight loop. The 50-term dot product per
// thread runs as 26 fma.rn.f32x2 on pairs loaded with ld.shared.v2.u64
// against pre-packed E registers. Exact pow-2 rescaling per step from the
// exponent of max(P[1..3]). Gold-score gathers hoisted to kernel start so
// their LDG latency overlaps E-table preparation instead of the serial tail.

constexpr int TT = 50;
constexpr int LL = 256;
constexpr int NTH = 128;
constexpr int STARTT = TT - 2;
constexpr int STOPT  = TT - 1;

#define LOG2E 1.4426950408889634f
#define LN2F  0.6931471805599453f

__device__ float    g_partial[1024];
__device__ unsigned g_done = 0;

__device__ __forceinline__ float ex2(float x) {
    float r;
    asm("ex2.approx.ftz.f32 %0, %1;" : "=f"(r) : "f"(x));
    return r;
}

__device__ __forceinline__ void barg(int id) {    // group barrier, 64 threads
    asm volatile("bar.sync %0, 64;" :: "r"(id));
}

#define PACK2(d, lo, hi) \
    asm("mov.b64 %0, {%1, %2};" : "=l"(d) : "f"(lo), "f"(hi))
#define UNPACK2(lo, hi, s) \
    asm("mov.b64 {%0, %1}, %2;" : "=f"(lo), "=f"(hi) : "l"(s))
#define FFMA2(d, a, b, c) \
    asm("fma.rn.f32x2 %0, %1, %2, %3;" : "=l"(d) : "l"(a), "l"(b), "l"(c))
#define FMUL2(d, a, b) \
    asm("mul.rn.f32x2 %0, %1, %2;" : "=l"(d) : "l"(a), "l"(b))
#define FADD2(d, a, b) \
    asm("add.rn.f32x2 %0, %1, %2;" : "=l"(d) : "l"(a), "l"(b))
#define LDS_V2U64(q0, q1, addr) \
    asm volatile("ld.shared.v2.u64 {%0, %1}, [%2];" \
                 : "=l"(q0), "=l"(q1) : "r"(addr))

__device__ __forceinline__ float blockSum(float v, volatile float* red) {
#pragma unroll
    for (int o = 16; o; o >>= 1) v += __shfl_xor_sync(0xffffffffu, v, o);
    if ((threadIdx.x & 31) == 0) red[threadIdx.x >> 5] = v;
    __syncthreads();
    v = (red[0] + red[1]) + (red[2] + red[3]);
    __syncthreads();
    return v;
}

__global__ void __launch_bounds__(NTH, 1)
crf_kernel(const float* __restrict__ feats, const float* __restrict__ trans,
           const int* __restrict__ tags, const int* __restrict__ mask,
           float* __restrict__ out) {
    __shared__ __align__(16) float Ab[2][64];   // alpha ping-pong
    __shared__ __align__(16) float Bb[2][64];   // beta  ping-pong
    __shared__ float red[4];
    __shared__ int s_len, s_kf, s_kb;
    __shared__ unsigned s_rank;

    const int b    = blockIdx.x;
    const int tid  = threadIdx.x;
    const bool isF = (tid < 64);       // forward group = warps 0-1
    const int g    = tid & 63;         // state index within group
    const bool gv  = (g < TT);
    const int gc   = gv ? g : (TT - 1);
    const int bid  = isF ? 1 : 2;

    if (tid == 0) s_len = 0;
    __syncthreads();

    // ---- sequence length (mask is a 0/1 prefix) ----
    {
        const int2* m2 = (const int2*)(mask + (size_t)b * LL);
        int2 v = m2[tid];
        int c = (v.x != 0) + (v.y != 0);
#pragma unroll
        for (int o = 16; o; o >>= 1) c += __shfl_xor_sync(0xffffffffu, c, o);
        if ((tid & 31) == 0) atomicAdd(&s_len, c);
    }

    const float* fb = feats + (size_t)b * LL * TT;
    const int*  tgb = tags + (size_t)b * LL;
    const float s0   = trans[STARTT * TT + 1];
    const float tref = trans[1 * TT + STOPT];
    const float C2f  = s0 * LOG2E;

    __syncthreads();
    const int len = s_len;
    const int nf  = (len - 1) >> 1;        // forward steps
    const int nb  = (len - 1) - nf;        // backward steps (>= nf)

    // ---- gold-score gathers HOISTED: LDG latency overlaps E-prep below ----
    float gl = 0.f;
    for (int t = tid; t < len; t += NTH) {
        int tg = tgb[t];
        int pv = (t == 0) ? STARTT : tgb[t - 1];
        gl += fb[t * TT + tg] + trans[pv * TT + tg];
    }

    // ---- E packed in registers: pair x holds (E[2x], E[2x+1]) of my slice
    //      forward thread j: E[i] = exp(trans[i][j]) (column)
    //      backward thread i: E[i] = exp(trans[i][x]) (row) ----
    const float* tb = isF ? (trans + gc) : (trans + gc * TT);
    const int    ts = isF ? TT : 1;
    uint64_t E2[26];
#pragma unroll
    for (int x = 0; x < 26; x++) {
        int i0 = 2 * x, i1 = 2 * x + 1;
        float e0 = (gv && i0 < TT) ? ex2(tb[i0 * ts] * LOG2E) : 0.f;
        float e1 = (gv && i1 < TT) ? ex2(tb[i1 * ts] * LOG2E) : 0.f;
        PACK2(E2[x], e0, e1);
    }

    // ---- group inits (all 64 slots written; cols >= 50 exact zero) ----
    if (isF) {
        Ab[0][g] = gv ? ex2((fb[gc] + trans[STARTT * TT + gc] - s0) * LOG2E)
                      : 0.f;
    } else {
        float w = gv ? ex2((trans[gc * TT + STOPT] - tref) * LOG2E) : 0.f;
        float f = (nb > 0) ? ex2(fb[(len - 1) * TT + gc] * LOG2E) : 1.f;
        Bb[0][g] = gv ? w * f : 0.f;
    }
    int kacc = 0;

    // ---- distance-2 feats prefetch (clamped once at init only) ----
    int r1 = isF ? 1 : len - 2;
    int r2 = isF ? 2 : len - 3;
    r1 = min(max(r1, 0), len - 1);
    r2 = min(max(r2, 0), len - 1);
    float fc = fb[r1 * TT + gc];
    float fn = fb[r2 * TT + gc];

    float* Pc = isF ? Ab[0] : Bb[0];
    float* Pn = isF ? Ab[1] : Bb[1];
    barg(bid);

    // one step: packed 52-term dot (26 FFMA2) + exact pow2 rescale + store
#define CRF_STEP(EFV)                                                       \
    {                                                                       \
        unsigned sc_ = (unsigned)__cvta_generic_to_shared(Pc);              \
        uint64_t q0, q1;                                                    \
        uint64_t acc0, acc1, acc2, acc3, acc4, acc5, acc6, acc7;            \
        LDS_V2U64(q0, q1, sc_);                                             \
        /* pivot from pair q1 = (P[2],P[3]) and q0.hi = P[1] */             \
        float pv0, pv1, pv2, pv3;                                           \
        UNPACK2(pv0, pv1, q0);                                              \
        UNPACK2(pv2, pv3, q1);                                              \
        float m_ = fmaxf(fmaxf(pv1, pv2), pv3);                             \
        int   k_ = (__float_as_int(m_) >> 23) - 127;                        \
        float sf = __int_as_float((127 - k_) << 23) * (EFV);                \
        FMUL2(acc0, q0, E2[0]);                                             \
        FMUL2(acc1, q1, E2[1]);                                             \
        LDS_V2U64(q0, q1, sc_ + 16);                                        \
        FMUL2(acc2, q0, E2[2]);                                             \
        FMUL2(acc3, q1, E2[3]);                                             \
        LDS_V2U64(q0, q1, sc_ + 32);                                        \
        FMUL2(acc4, q0, E2[4]);                                             \
        FMUL2(acc5, q1, E2[5]);                                             \
        LDS_V2U64(q0, q1, sc_ + 48);                                        \
        FMUL2(acc6, q0, E2[6]);                                             \
        FMUL2(acc7, q1, E2[7]);                                             \
        _Pragma("unroll")                                                   \
        for (int q = 4; q < 13; q++) {                                      \
            LDS_V2U64(q0, q1, sc_ + q * 16);                                \
            FFMA2(acc0, q0, E2[2 * q], acc0);                               \
            FFMA2(acc1, q1, E2[2 * q + 1], acc1);                           \
            uint64_t t0 = acc0; acc0 = acc2; acc2 = acc4; acc4 = acc6;      \
            acc6 = t0;                                                      \
            uint64_t t1 = acc1; acc1 = acc3; acc3 = acc5; acc5 = acc7;      \
            acc7 = t1;                                                      \
        }                                                                   \
        FADD2(acc0, acc0, acc4);                                            \
        FADD2(acc1, acc1, acc5);                                            \
        FADD2(acc2, acc2, acc6);                                            \
        FADD2(acc3, acc3, acc7);                                            \
        FADD2(acc0, acc0, acc2);                                            \
        FADD2(acc1, acc1, acc3);                                            \
        FADD2(acc0, acc0, acc1);                                            \
        float lo_, hi_;                                                     \
        UNPACK2(lo_, hi_, acc0);                                            \
        Pn[g] = (lo_ + hi_) * sf;                                           \
        kacc += k_;                                                         \
        barg(bid);                                                          \
        float* _t = Pc; Pc = Pn; Pn = _t;                                   \
    }

    if (isF) {
        for (int s = 1; s <= nf; ++s) {
            float efv = ex2(fc * LOG2E);
            fc = fn;
            fn = fb[(s + 2) * TT + gc];       // s+2 <= 129 < LL: in-bounds
            CRF_STEP(efv);
        }
    } else {
        for (int s = 1; s < nb; ++s) {
            float efv = ex2(fc * LOG2E);
            fc = fn;
            fn = fb[(len - 3 - s) * TT + gc]; // >= nf-1 >= 0 when loop runs
            CRF_STEP(efv);
        }
        if (nb >= 1) {                  // final step: exclude ef_m
            CRF_STEP(1.0f);
        }
    }
#undef CRF_STEP

    // ---- combine at the midpoint: Z = sum_i alpha_m[i] * beta_m[i] ----
    if (tid == 0)  s_kf = kacc;
    if (tid == 64) s_kb = kacc;
    __syncthreads();
    float z = 0.f;
    if (isF && gv) z = Pc[g] * Bb[nb & 1][g];
    float sumv = blockSum(z, red);
    float fwd = (log2f(sumv) + C2f + (float)(s_kf + s_kb)) * LN2F + tref;

    // ---- gold score: gathers already done, only the reduction remains ----
    float gold = blockSum(gl, red);

    if (tid == 0) {
        gold += trans[tgb[len - 1] * TT + STOPT];
        g_partial[b] = fwd - gold;
    }

    // ---- fused finalize: last CTA sums all partials (fixed order) ----
    __threadfence();
    if (tid == 0) s_rank = atomicAdd(&g_done, 1u);
    __syncthreads();
    if (s_rank == gridDim.x - 1) {
        const int B = gridDim.x;
        if (tid < 32) {
            float acc = 0.f;
            for (int i = tid; i < B; i += 32) {
                float v;
                asm volatile("ld.global.cg.f32 %0, [%1];" : "=f"(v)
                             : "l"(&g_partial[i]));
                acc += v;
            }
#pragma unroll
            for (int o = 16; o; o >>= 1)
                acc += __shfl_xor_sync(0xffffffffu, acc, o);
            if (tid == 0) {
                *out = acc;
                g_done = 0;   // reset for next graph replay
            }
        }
    }
}

extern "C" void kernel_launch(void* const* d_in, const int* in_sizes, int n_in,
                              void* d_out, int out_size) {
    const float* feats = (const float*)d_in[0];
    const float* trans = (const float*)d_in[1];
    const int*   tags  = (const int*)d_in[2];
    const int*   mask  = (const int*)d_in[3];
    int B = in_sizes[0] / (LL * TT);

    crf_kernel<<<B, NTH>>>(feats, trans, tags, mask, (float*)d_out);
}